// round 16
// baseline (speedup 1.0000x reference)
#include <cuda_runtime.h>

#define IMG 224
#define CS 8
#define NBINS 8
#define HC 28                      // cells per dim
#define FEAT (HC * HC * NBINS)     // 6272 per image
#define SROWS 32                   // pixel rows per strip
#define NSTRIPS (IMG / SROWS)      // 7
#define LROWS (SROWS + 2)          // 34 gray rows incl vertical halo
#define SSTRIDE 232                // smem row stride (floats)
#define NTH 448                    // 2 x (one thread per column)
#define ROW4 (IMG / 4)             // 56 float4 per image row
#define MAXB 1024

// Gaussian (SIGMA=1, CS=8) separable: g[p][c] = GY(p)*GX(c), coords p-3.5
#define GW3 0.0021874911f          // exp(-6.125)
#define GW2 0.0439369336f          // exp(-3.125)
#define GW1 0.3246524674f          // exp(-1.125)
#define GW0 0.8824969026f          // exp(-0.125)
#define GY(p) (((p)==0||(p)==7) ? GW3 : ((p)==1||(p)==6) ? GW2 : ((p)==2||(p)==5) ? GW1 : GW0)

__device__ float        g_partial[MAXB * NSTRIPS];  // per (image, strip) sum of squares
__device__ unsigned int g_count[MAXB];              // zero-init; restored to 0 every call

__global__ void __launch_bounds__(NTH, 4)
hog_kernel(const float* __restrict__ x,
           float* __restrict__ out) {
    const int s   = blockIdx.x;     // strip of 32 pixel rows
    const int b   = blockIdx.y;     // image
    const int tid = threadIdx.x;
    const int lane = tid & 31;
    const int warp = tid >> 5;

    __shared__ float sgray[LROWS * SSTRIDE];
    __shared__ float wsum[NTH / 32];
    __shared__ unsigned int s_arrive;
    __shared__ float s_inv;

    // Zero side padding: only cols 3 and 228 of each row are ever read as halo
    if (tid < LROWS) {
        sgray[tid * SSTRIDE + 3]   = 0.0f;
        sgray[tid * SSTRIDE + 228] = 0.0f;
    }

    // ---- Gray fill: 448 threads = 8 rows x 56 float4 per iteration, 34 rows ----
    const float* xb  = x + (size_t)b * 3 * IMG * IMG;
    const int    gr0 = s * SROWS - 1;
    {
        const int r0 = tid / ROW4;       // 0..7
        const int q  = tid - r0 * ROW4;  // 0..55
        if (s != 0 && s != NSTRIPS - 1) {
            // interior strip: all rows in-bounds, unconditional loads
#pragma unroll
            for (int it = 0; it < 5; it++) {
                const int rr = r0 + it * 8;
                if (rr < LROWS) {
                    const float* base = xb + (gr0 + rr) * IMG + q * 4;
                    float4 r4 = *(const float4*)(base);
                    float4 g4 = *(const float4*)(base + IMG * IMG);
                    float4 b4 = *(const float4*)(base + 2 * IMG * IMG);
                    float4 o;
                    o.x = fmaf(0.2989f, r4.x, fmaf(0.587f, g4.x, 0.114f * b4.x));
                    o.y = fmaf(0.2989f, r4.y, fmaf(0.587f, g4.y, 0.114f * b4.y));
                    o.z = fmaf(0.2989f, r4.z, fmaf(0.587f, g4.z, 0.114f * b4.z));
                    o.w = fmaf(0.2989f, r4.w, fmaf(0.587f, g4.w, 0.114f * b4.w));
                    *(float4*)(sgray + rr * SSTRIDE + 4 + q * 4) = o;
                }
            }
        } else {
#pragma unroll
            for (int it = 0; it < 5; it++) {
                const int rr = r0 + it * 8;
                if (rr < LROWS) {
                    const int gr = gr0 + rr;
                    float4 o = make_float4(0.f, 0.f, 0.f, 0.f);
                    if (gr >= 0 && gr < IMG) {
                        const float* base = xb + gr * IMG + q * 4;
                        float4 r4 = *(const float4*)(base);
                        float4 g4 = *(const float4*)(base + IMG * IMG);
                        float4 b4 = *(const float4*)(base + 2 * IMG * IMG);
                        o.x = fmaf(0.2989f, r4.x, fmaf(0.587f, g4.x, 0.114f * b4.x));
                        o.y = fmaf(0.2989f, r4.y, fmaf(0.587f, g4.y, 0.114f * b4.y));
                        o.z = fmaf(0.2989f, r4.z, fmaf(0.587f, g4.z, 0.114f * b4.z));
                        o.w = fmaf(0.2989f, r4.w, fmaf(0.587f, g4.w, 0.114f * b4.w));
                    }
                    *(float4*)(sgray + rr * SSTRIDE + 4 + q * 4) = o;
                }
            }
        }
    }
    __syncthreads();

    // ---- Compute: thread = one column x one 16-row half of the strip ----
    const int h2 = tid / 224;        // 0 = rows 0-15, 1 = rows 16-31 of strip
    const int c  = tid - h2 * 224;   // pixel column
    const float* col = sgray + (h2 * 16) * SSTRIDE + 4 + c;

    // Column Gaussian factor (folded into reconstruct): hg = 0.5 * GX(c&7)
    const int c7 = c & 7;
    const int dcq = min(c7, 7 - c7);   // 0..3
    const float gxc = (dcq == 3) ? GW0 : (dcq == 2) ? GW1 : (dcq == 1) ? GW2 : GW3;
    const float hg = 0.5f * gxc;

    float t0, t1, d0, d1;
    {
        float a = col[-1], m = col[0], z = col[1];
        t0 = fmaf(2.0f, m, a + z);  d0 = z - a;
        a = col[SSTRIDE - 1]; m = col[SSTRIDE]; z = col[SSTRIDE + 1];
        t1 = fmaf(2.0f, m, a + z);  d1 = z - a;
    }

    float ssq = 0.0f;
    float* ob = out + (size_t)b * FEAT + (s * 4 + h2 * 2) * 224;

#pragma unroll
    for (int half = 0; half < 2; half++) {
        // Cumulative-class accumulation. Classes nested: pD => pA => pS.
        float T = 0.f, A = 0.f, D = 0.f, S = 0.f;
        float Td = 0.f, Ad = 0.f, Dd = 0.f, Sd = 0.f;

#pragma unroll
        for (int p = 0; p < 8; p++) {
            const int rr = half * 8 + p + 2;
            float a = col[rr * SSTRIDE - 1];
            float m = col[rr * SSTRIDE];
            float z = col[rr * SSTRIDE + 1];
            float t2 = fmaf(2.0f, m, a + z);
            float d2 = z - a;

            float gx = fmaf(2.0f, d1, d0) + d2;
            float gy = t2 - t0;

            float s2 = fmaf(gy, gy, fmaf(gx, gx, 1e-6f));
            float mag;
            asm("sqrt.approx.f32 %0, %1;" : "=f"(mag) : "f"(s2));
            float w = mag * GY(p);     // compile-time immediate multiplier

            const bool sn  = gy < 0.0f;
            float gx2 = sn ? -gx : gx;
            float sgn = sn ? -1.0f : 1.0f;
            float ay  = fabsf(gy);

            float wA = (gx2 > 0.0f) ? w : 0.0f;   // class pA
            float wD = (ay  < gx2 ) ? w : 0.0f;   // class pD (subset of pA)
            float wS = (ay  > -gx2) ? w : 0.0f;   // class pS (superset of pA)

            T += w;   Td = fmaf(sgn, w,  Td);
            A += wA;  Ad = fmaf(sgn, wA, Ad);
            D += wD;  Dd = fmaf(sgn, wD, Dd);
            S += wS;  Sd = fmaf(sgn, wS, Sd);

            t0 = t1; t1 = t2; d0 = d1; d1 = d2;
        }

        // Recover per-class sums (nested classes -- no cancellation)
        float hs[4], hd[4];
        hs[0] = D;      hd[0] = Dd;
        hs[1] = A - D;  hd[1] = Ad - Dd;
        hs[2] = S - A;  hd[2] = Sd - Ad;
        hs[3] = T - S;  hd[3] = Td - Sd;

        // Reconstruct 8 bins with column-Gaussian folded in
        float h[NBINS];
#pragma unroll
        for (int k = 0; k < 4; k++) {
            float e = hg * hs[k];
            h[k]     = fmaf( hg, hd[k], e);
            h[k + 4] = fmaf(-hg, hd[k], e);
        }

        // 8-lane multi-bin fold: within each 8-lane cell group, lane ends with bin = lane&7
        const bool q4 = (lane & 4) != 0;
        float s0 = q4 ? h[0] : h[4];
        float s1 = q4 ? h[1] : h[5];
        float s2_ = q4 ? h[2] : h[6];
        float s3 = q4 ? h[3] : h[7];
        float a0 = (q4 ? h[4] : h[0]) + __shfl_xor_sync(0xffffffffu, s0, 4);
        float a1 = (q4 ? h[5] : h[1]) + __shfl_xor_sync(0xffffffffu, s1, 4);
        float a2 = (q4 ? h[6] : h[2]) + __shfl_xor_sync(0xffffffffu, s2_, 4);
        float a3 = (q4 ? h[7] : h[3]) + __shfl_xor_sync(0xffffffffu, s3, 4);

        const bool q2 = (lane & 2) != 0;
        float u0 = q2 ? a0 : a2;
        float u1 = q2 ? a1 : a3;
        float c0 = (q2 ? a2 : a0) + __shfl_xor_sync(0xffffffffu, u0, 2);
        float c1 = (q2 ? a3 : a1) + __shfl_xor_sync(0xffffffffu, u1, 2);

        const bool q1 = (lane & 1) != 0;
        float v_ = q1 ? c0 : c1;
        float dsum = (q1 ? c1 : c0) + __shfl_xor_sync(0xffffffffu, v_, 1);

        // Coalesced: out[b][ (s*4 + h2*2 + half)*28 + c/8 ][ c&7 ]
        ob[half * 224 + c] = dsum;
        ssq = fmaf(dsum, dsum, ssq);
    }

    // Block sum of squares -> deterministic per-strip partial
#pragma unroll
    for (int o = 16; o > 0; o >>= 1)
        ssq += __shfl_xor_sync(0xffffffffu, ssq, o);
    if (lane == 0) wsum[warp] = ssq;
    __syncthreads();
    if (tid == 0) {
        float t = 0.0f;
#pragma unroll
        for (int w = 0; w < NTH / 32; w++) t += wsum[w];
        g_partial[b * NSTRIPS + s] = t;
    }

    // ---- Fused normalization: last arriving block for image b scales it ----
    __threadfence();                       // publish out rows + g_partial
    if (tid == 0) s_arrive = atomicAdd(&g_count[b], 1u);
    __syncthreads();
    if (s_arrive == NSTRIPS - 1) {
        __threadfence();                   // acquire other strips' writes
        if (tid == 0) {
            float t = 0.0f;
#pragma unroll
            for (int i = 0; i < NSTRIPS; i++) t += g_partial[b * NSTRIPS + i];
            s_inv = 1.0f / (sqrtf(t) + 1e-6f);
            g_count[b] = 0;                // restore for next launch / replay
        }
        __syncthreads();
        const float inv = s_inv;
        float4* o4 = (float4*)(out + (size_t)b * FEAT);
        for (int i = tid; i < FEAT / 4; i += NTH) {   // 1568 / 448 -> 4 iters (last partial)
            float4 v = o4[i];
            v.x *= inv; v.y *= inv; v.z *= inv; v.w *= inv;
            o4[i] = v;
        }
    }
}

extern "C" void kernel_launch(void* const* d_in, const int* in_sizes, int n_in,
                              void* d_out, int out_size) {
    const float* x = (const float*)d_in[0];
    float* out = (float*)d_out;

    const int bs = in_sizes[0] / (3 * IMG * IMG);

    dim3 grid(NSTRIPS, bs);
    hog_kernel<<<grid, NTH>>>(x, out);
}

// round 17
// speedup vs baseline: 1.0475x; 1.0475x over previous
#include <cuda_runtime.h>
#include <cstdint>

#define IMG 224
#define CS 8
#define NBINS 8
#define HC 28                      // cells per dim
#define FEAT (HC * HC * NBINS)     // 6272 per image
#define SROWS 16                   // pixel rows per strip
#define NSTRIPS (IMG / SROWS)      // 14
#define LROWS (SROWS + 2)          // 18 gray rows incl vertical halo
#define SSTRIDE 232                // smem row stride (floats)
#define NTH 224                    // one thread per column
#define ROW4 (IMG / 4)             // 56 float4 per image row
#define MAXB 1024

// Gaussian (SIGMA=1, CS=8) separable: g[p][c] = GY(p)*GX(c), coords p-3.5
#define GW3 0.0021874911f          // exp(-6.125)
#define GW2 0.0439369336f          // exp(-3.125)
#define GW1 0.3246524674f          // exp(-1.125)
#define GW0 0.8824969026f          // exp(-0.125)
#define GY(p) (((p)==0||(p)==7) ? GW3 : ((p)==1||(p)==6) ? GW2 : ((p)==2||(p)==5) ? GW1 : GW0)

__device__ float        g_partial[MAXB * NSTRIPS];  // per (image, strip) sum of squares
__device__ unsigned int g_count[MAXB];              // zero-init; restored to 0 every call

// ---- packed f32x2 helpers ----
#define PACK2(out64, lo, hi) \
    asm("mov.b64 %0, {%1, %2};" : "=l"(out64) : "f"(lo), "f"(hi))
#define UNPACK2(lo, hi, in64) \
    asm("mov.b64 {%0, %1}, %2;" : "=f"(lo), "=f"(hi) : "l"(in64))

// o = 0.2989*r + 0.587*g + 0.114*b on two packed lanes
__device__ __forceinline__ uint64_t gray_f32x2(uint64_t r2, uint64_t g2, uint64_t b2,
                                               uint64_t c2989, uint64_t c587, uint64_t c114) {
    uint64_t t, o;
    asm("mul.rn.f32x2 %0, %1, %2;"      : "=l"(t) : "l"(b2), "l"(c114));
    asm("fma.rn.f32x2 %0, %1, %2, %3;"  : "=l"(t) : "l"(g2), "l"(c587), "l"(t));
    asm("fma.rn.f32x2 %0, %1, %2, %3;"  : "=l"(o) : "l"(r2), "l"(c2989), "l"(t));
    return o;
}

__device__ __forceinline__ float4 gray4(float4 r4, float4 g4, float4 b4,
                                        uint64_t c2989, uint64_t c587, uint64_t c114) {
    uint64_t rxy, rzw, gxy, gzw, bxy, bzw;
    PACK2(rxy, r4.x, r4.y);  PACK2(rzw, r4.z, r4.w);
    PACK2(gxy, g4.x, g4.y);  PACK2(gzw, g4.z, g4.w);
    PACK2(bxy, b4.x, b4.y);  PACK2(bzw, b4.z, b4.w);
    uint64_t oxy = gray_f32x2(rxy, gxy, bxy, c2989, c587, c114);
    uint64_t ozw = gray_f32x2(rzw, gzw, bzw, c2989, c587, c114);
    float4 o;
    UNPACK2(o.x, o.y, oxy);
    UNPACK2(o.z, o.w, ozw);
    return o;
}

__global__ void __launch_bounds__(NTH, 9)
hog_kernel(const float* __restrict__ x,
           float* __restrict__ out) {
    const int s   = blockIdx.x;     // strip
    const int b   = blockIdx.y;     // image
    const int tid = threadIdx.x;
    const int lane = tid & 31;
    const int warp = tid >> 5;

    __shared__ float sgray[LROWS * SSTRIDE];
    __shared__ float wsum[NTH / 32];
    __shared__ unsigned int s_arrive;
    __shared__ float s_inv;

    // Zero side padding: only cols 3 and 228 of each row are ever read as halo
    if (tid < LROWS) {
        sgray[tid * SSTRIDE + 3]   = 0.0f;
        sgray[tid * SSTRIDE + 228] = 0.0f;
    }

    // packed gray-conversion constants
    uint64_t c2989, c587, c114;
    PACK2(c2989, 0.2989f, 0.2989f);
    PACK2(c587,  0.587f,  0.587f);
    PACK2(c114,  0.114f,  0.114f);

    // ---- Gray fill: statically unrolled, predicated iterations (front-batched LDG) ----
    const float* xb  = x + (size_t)b * 3 * IMG * IMG;
    const int    gr0 = s * SROWS - 1;
    {
        const int r0 = tid / ROW4;       // 0..3
        const int q  = tid - r0 * ROW4;  // 0..55
        if (s != 0 && s != NSTRIPS - 1) {
            // interior strip: all rows in-bounds, unconditional loads
#pragma unroll
            for (int it = 0; it < 5; it++) {
                const int rr = r0 + it * 4;
                if (rr < LROWS) {
                    const float* base = xb + (gr0 + rr) * IMG + q * 4;
                    float4 r4 = *(const float4*)(base);
                    float4 g4 = *(const float4*)(base + IMG * IMG);
                    float4 b4 = *(const float4*)(base + 2 * IMG * IMG);
                    float4 o = gray4(r4, g4, b4, c2989, c587, c114);
                    *(float4*)(sgray + rr * SSTRIDE + 4 + q * 4) = o;
                }
            }
        } else {
#pragma unroll
            for (int it = 0; it < 5; it++) {
                const int rr = r0 + it * 4;
                if (rr < LROWS) {
                    const int gr = gr0 + rr;
                    float4 o = make_float4(0.f, 0.f, 0.f, 0.f);
                    if (gr >= 0 && gr < IMG) {
                        const float* base = xb + gr * IMG + q * 4;
                        float4 r4 = *(const float4*)(base);
                        float4 g4 = *(const float4*)(base + IMG * IMG);
                        float4 b4 = *(const float4*)(base + 2 * IMG * IMG);
                        o = gray4(r4, g4, b4, c2989, c587, c114);
                    }
                    *(float4*)(sgray + rr * SSTRIDE + 4 + q * 4) = o;
                }
            }
        }
    }
    __syncthreads();

    // One thread per column: separable Sobel with rolling rows.
    const float* col = sgray + tid + 4;

    // Column Gaussian factor (folded into reconstruct): hg = 0.5 * GX(tid&7)
    const int c7 = tid & 7;
    const int dcq = min(c7, 7 - c7);   // 0..3
    const float gxc = (dcq == 3) ? GW0 : (dcq == 2) ? GW1 : (dcq == 1) ? GW2 : GW3;
    const float hg = 0.5f * gxc;

    float t0, t1, d0, d1;
    {
        float a = col[-1], m = col[0], z = col[1];
        t0 = fmaf(2.0f, m, a + z);  d0 = z - a;
        a = col[SSTRIDE - 1]; m = col[SSTRIDE]; z = col[SSTRIDE + 1];
        t1 = fmaf(2.0f, m, a + z);  d1 = z - a;
    }

    float ssq = 0.0f;
    float* ob = out + (size_t)b * FEAT + s * 2 * 224;

#pragma unroll
    for (int half = 0; half < 2; half++) {
        // Cumulative-class accumulation. Classes nested: pD => pA => pS.
        float T = 0.f, A = 0.f, D = 0.f, S = 0.f;
        float Td = 0.f, Ad = 0.f, Dd = 0.f, Sd = 0.f;

#pragma unroll
        for (int p = 0; p < 8; p++) {
            const int rr = half * 8 + p + 2;
            float a = col[rr * SSTRIDE - 1];
            float m = col[rr * SSTRIDE];
            float z = col[rr * SSTRIDE + 1];
            float t2 = fmaf(2.0f, m, a + z);
            float d2 = z - a;

            float gx = fmaf(2.0f, d1, d0) + d2;
            float gy = t2 - t0;

            float s2 = fmaf(gy, gy, fmaf(gx, gx, 1e-6f));
            float mag;
            asm("sqrt.approx.f32 %0, %1;" : "=f"(mag) : "f"(s2));
            float w = mag * GY(p);     // compile-time immediate multiplier

            const bool sn  = gy < 0.0f;
            float gx2 = sn ? -gx : gx;
            float sgn = sn ? -1.0f : 1.0f;
            float ay  = fabsf(gy);

            float wA = (gx2 > 0.0f) ? w : 0.0f;   // class pA
            float wD = (ay  < gx2 ) ? w : 0.0f;   // class pD (subset of pA)
            float wS = (ay  > -gx2) ? w : 0.0f;   // class pS (superset of pA)

            T += w;   Td = fmaf(sgn, w,  Td);
            A += wA;  Ad = fmaf(sgn, wA, Ad);
            D += wD;  Dd = fmaf(sgn, wD, Dd);
            S += wS;  Sd = fmaf(sgn, wS, Sd);

            t0 = t1; t1 = t2; d0 = d1; d1 = d2;
        }

        // Recover per-class sums (nested classes -- no cancellation)
        float hs[4], hd[4];
        hs[0] = D;      hd[0] = Dd;
        hs[1] = A - D;  hd[1] = Ad - Dd;
        hs[2] = S - A;  hd[2] = Sd - Ad;
        hs[3] = T - S;  hd[3] = Td - Sd;

        // Reconstruct 8 bins with column-Gaussian folded in
        float h[NBINS];
#pragma unroll
        for (int k = 0; k < 4; k++) {
            float e = hg * hs[k];
            h[k]     = fmaf( hg, hd[k], e);
            h[k + 4] = fmaf(-hg, hd[k], e);
        }

        // 8-lane multi-bin fold: within each 8-lane cell group, lane ends with bin = lane&7
        const bool q4 = (lane & 4) != 0;
        float s0 = q4 ? h[0] : h[4];
        float s1 = q4 ? h[1] : h[5];
        float s2_ = q4 ? h[2] : h[6];
        float s3 = q4 ? h[3] : h[7];
        float a0 = (q4 ? h[4] : h[0]) + __shfl_xor_sync(0xffffffffu, s0, 4);
        float a1 = (q4 ? h[5] : h[1]) + __shfl_xor_sync(0xffffffffu, s1, 4);
        float a2 = (q4 ? h[6] : h[2]) + __shfl_xor_sync(0xffffffffu, s2_, 4);
        float a3 = (q4 ? h[7] : h[3]) + __shfl_xor_sync(0xffffffffu, s3, 4);

        const bool q2 = (lane & 2) != 0;
        float u0 = q2 ? a0 : a2;
        float u1 = q2 ? a1 : a3;
        float c0 = (q2 ? a2 : a0) + __shfl_xor_sync(0xffffffffu, u0, 2);
        float c1 = (q2 ? a3 : a1) + __shfl_xor_sync(0xffffffffu, u1, 2);

        const bool q1 = (lane & 1) != 0;
        float v_ = q1 ? c0 : c1;
        float dsum = (q1 ? c1 : c0) + __shfl_xor_sync(0xffffffffu, v_, 1);

        // Coalesced: out[b][ (s*2+half)*28 + tid/8 ][ tid&7 ]
        ob[half * 224 + tid] = dsum;
        ssq = fmaf(dsum, dsum, ssq);
    }

    // Block sum of squares -> deterministic per-strip partial
#pragma unroll
    for (int o = 16; o > 0; o >>= 1)
        ssq += __shfl_xor_sync(0xffffffffu, ssq, o);
    if (lane == 0) wsum[warp] = ssq;
    __syncthreads();
    if (tid == 0) {
        float t = 0.0f;
#pragma unroll
        for (int w = 0; w < NTH / 32; w++) t += wsum[w];
        g_partial[b * NSTRIPS + s] = t;
    }

    // ---- Fused normalization: last arriving block for image b scales it ----
    __threadfence();                       // publish out rows + g_partial
    if (tid == 0) s_arrive = atomicAdd(&g_count[b], 1u);
    __syncthreads();
    if (s_arrive == NSTRIPS - 1) {
        __threadfence();                   // acquire other strips' writes
        if (tid == 0) {
            float t = 0.0f;
#pragma unroll
            for (int i = 0; i < NSTRIPS; i++) t += g_partial[b * NSTRIPS + i];
            s_inv = 1.0f / (sqrtf(t) + 1e-6f);
            g_count[b] = 0;                // restore for next launch / replay
        }
        __syncthreads();
        const float inv = s_inv;
        float4* o4 = (float4*)(out + (size_t)b * FEAT);
#pragma unroll
        for (int i = 0; i < FEAT / 4 / NTH; i++) {   // 7 iterations
            float4 v = o4[i * NTH + tid];
            v.x *= inv; v.y *= inv; v.z *= inv; v.w *= inv;
            o4[i * NTH + tid] = v;
        }
    }
}

extern "C" void kernel_launch(void* const* d_in, const int* in_sizes, int n_in,
                              void* d_out, int out_size) {
    const float* x = (const float*)d_in[0];
    float* out = (float*)d_out;

    const int bs = in_sizes[0] / (3 * IMG * IMG);

    dim3 grid(NSTRIPS, bs);
    hog_kernel<<<grid, NTH>>>(x, out);
}